// round 10
// baseline (speedup 1.0000x reference)
#include <cuda_runtime.h>
#include <cuda_fp16.h>
#include <mma.h>
#include <cstdint>

using namespace nvcuda;

#define N_NODES 100000
#define N_EDGES 640000
#define WID     128
#define NFEAT   64
#define KE      192      // WID + NFEAT
#define KM      256      // 2*WID

// ---- ygemm kernel smem: sA [128][136]h + sB [128][136]h; sC f32 overlays ----
#define YG_LD   136
#define C_LD    132
#define YG_SA   0
#define YG_SB   34816
#define SMEM_YG (2 * 34816)                       // 69632 -> occ 2

// ---- edge kernel smem (64-edge tile) ----
#define EG_LD    136
#define EF_LD2   72
#define EG_OFF_DST  0                              // int[64]
#define EG_OFF_PRE  512                            // [64][136]h = 17408
#define EG_OFF_XS   (512 + 17408)                  // 17920
#define EG_OFF_R3   (17920 + 17408)                // 35328
#define EG_OFF_FEAT EG_OFF_R3                      // [64][72]h = 9216
#define EG_OFF_W2   (EG_OFF_R3 + 9216)             // [64][136]h = 17408 -> 61952
#define EG_OFF_C    EG_OFF_R3                      // f32 [64][132] = 33792 overlay
#define SMEM_EDGE   (EG_OFF_R3 + 33792)            // 69120 -> occ 3

// ---- node kernel smem: sA [128][264]h (sC overlays) + sB chunk [128][136]h ----
#define A_LD_N  264
#define B_LD    136
#define SA_N_BYTES (128*A_LD_N*2)                  // 67584
#define SMEM_NODE (SA_N_BYTES + 128*B_LD*2)        // 102400 -> occ 2

#define HNEG_INF2 0xFC00FC00u

// ---------- scratch ----------
__device__ unsigned g_maxes[(size_t)N_NODES * (WID/2)];       // f16x2: max(relu - x[src])
__device__ __align__(16) __half g_xh[(size_t)N_NODES * WID];  // fp16 x image
__device__ __align__(16) __half g_y[(size_t)N_NODES * WID];   // fp16 y = x @ W1
__device__ __half   g_We[KE * WID];
__device__ __half   g_Wm[KM * WID];

__device__ __forceinline__ void red_max_h4(unsigned* addr, unsigned v01, unsigned v23) {
    unsigned short a = (unsigned short)(v01 & 0xFFFFu);
    unsigned short b = (unsigned short)(v01 >> 16);
    unsigned short c = (unsigned short)(v23 & 0xFFFFu);
    unsigned short d = (unsigned short)(v23 >> 16);
    asm volatile("red.global.v4.f16.max.noftz [%0], {%1, %2, %3, %4};"
                 :: "l"(addr), "h"(a), "h"(b), "h"(c), "h"(d) : "memory");
}
// maxes word + xh word -> f16x2 node-input word; -inf (empty segment) -> 0
__device__ __forceinline__ unsigned combine_max(unsigned m, unsigned xw) {
    __half2 mh = *(__half2*)&m;
    __half2 xv = *(__half2*)&xw;
    float lo = ((m & 0xFFFFu) == 0xFC00u) ? 0.0f : __low2float(mh)  + __low2float(xv);
    float hi = ((m >> 16)     == 0xFC00u) ? 0.0f : __high2float(mh) + __high2float(xv);
    __half2 r = __floats2half2_rn(lo, hi);
    return *(unsigned*)&r;
}

// ---------- kernel 0: prep ----------
__global__ void prep_kernel(const float* __restrict__ x,
                            const float* __restrict__ We, const float* __restrict__ Wm) {
    int i = blockIdx.x * blockDim.x + threadIdx.x;
    if (i < N_NODES * WID / 4) {
        float4 v = ((const float4*)x)[i];
        __half2 h0 = __floats2half2_rn(v.x, v.y);
        __half2 h1 = __floats2half2_rn(v.z, v.w);
        ((uint2*)g_xh)[i] = make_uint2(*(unsigned*)&h0, *(unsigned*)&h1);
    }
    if (i < N_NODES * (WID/2) / 4)
        ((uint4*)g_maxes)[i] = make_uint4(HNEG_INF2, HNEG_INF2, HNEG_INF2, HNEG_INF2);
    if (i < KE * WID) g_We[i] = __float2half_rn(We[i]);
    if (i < KM * WID) g_Wm[i] = __float2half_rn(Wm[i]);
}

// ---------- kernel 1: y = xh @ W1 (dense, 128-row tiles) ----------
__global__ __launch_bounds__(256, 2)
void ygemm_kernel() {
    extern __shared__ __align__(16) char smem[];
    __half* sA = (__half*)(smem + YG_SA);    // [128][136]
    __half* sB = (__half*)(smem + YG_SB);    // [128][136] = W1
    float*  sC = (float*)smem;               // [128][132] overlays sA/sB post-GEMM

    const int tid  = threadIdx.x;
    const int lane = tid & 31;
    const int wid  = tid >> 5;
    const int nbase = blockIdx.x * 128;
    const int wm = wid & 3, wn = wid >> 2;

    // stage W1 = g_We rows 0..127
    {
        const uint4* gB = (const uint4*)g_We;
        for (int i = tid; i < 128 * 16; i += 256) {
            int k = i >> 4, c = i & 15;
            *((uint4*)(sB + k * YG_LD) + c) = gB[i];
        }
    }
    // stage A from xh image
    const uint2* xh = (const uint2*)g_xh;
    #pragma unroll 4
    for (int it = 0; it < 16; ++it) {
        int r = wid * 16 + it;
        int node = nbase + r;
        *(uint2*)(sA + r * YG_LD + lane * 4) =
            (node < N_NODES) ? xh[(size_t)node * 32 + lane] : make_uint2(0u, 0u);
    }
    __syncthreads();

    wmma::fragment<wmma::accumulator, 16, 16, 16, float> c[2][4];
    #pragma unroll
    for (int i = 0; i < 2; i++)
        #pragma unroll
        for (int j = 0; j < 4; j++) wmma::fill_fragment(c[i][j], 0.0f);

    #pragma unroll
    for (int k = 0; k < 8; ++k) {
        wmma::fragment<wmma::matrix_a, 16, 16, 16, __half, wmma::row_major> a[2];
        wmma::load_matrix_sync(a[0], sA + (wm * 32 +  0) * YG_LD + k * 16, YG_LD);
        wmma::load_matrix_sync(a[1], sA + (wm * 32 + 16) * YG_LD + k * 16, YG_LD);
        #pragma unroll
        for (int j = 0; j < 4; j++) {
            wmma::fragment<wmma::matrix_b, 16, 16, 16, __half, wmma::row_major> b;
            wmma::load_matrix_sync(b, sB + (k * 16) * YG_LD + wn * 64 + j * 16, YG_LD);
            wmma::mma_sync(c[0][j], a[0], b, c[0][j]);
            wmma::mma_sync(c[1][j], a[1], b, c[1][j]);
        }
    }
    __syncthreads();

    #pragma unroll
    for (int i = 0; i < 2; i++)
        #pragma unroll
        for (int j = 0; j < 4; j++)
            wmma::store_matrix_sync(sC + (wm * 32 + i * 16) * C_LD + wn * 64 + j * 16,
                                    c[i][j], C_LD, wmma::mem_row_major);
    __syncthreads();

    #pragma unroll 4
    for (int it = 0; it < 16; ++it) {
        int r = wid * 16 + it;
        int node = nbase + r;
        if (node >= N_NODES) continue;
        const float* crow = sC + r * C_LD + lane * 4;
        __half2 h0 = __floats2half2_rn(crow[0], crow[1]);
        __half2 h1 = __floats2half2_rn(crow[2], crow[3]);
        ((uint2*)g_y)[(size_t)node * 32 + lane] =
            make_uint2(*(unsigned*)&h0, *(unsigned*)&h1);
    }
}

// ---------- kernel 2: edge MLP (K=64) + shifted segment-max ----------
// 128 threads, 64 edges/block
__global__ __launch_bounds__(128, 3)
void edge_kernel(const int* __restrict__ e, const float* __restrict__ efeat,
                 const float* __restrict__ b_edge) {
    extern __shared__ __align__(16) char smem[];
    int*    sDst  = (int*)(smem + EG_OFF_DST);
    __half* sPre  = (__half*)(smem + EG_OFF_PRE);    // [64][136] y[dst]-y[src]
    __half* sXs   = (__half*)(smem + EG_OFF_XS);     // [64][136] x[src]
    __half* sFeat = (__half*)(smem + EG_OFF_FEAT);   // [64][72]
    __half* sW2   = (__half*)(smem + EG_OFF_W2);     // [64][136] W_edge rows 128..191
    float*  sC    = (float*)(smem + EG_OFF_C);       // [64][132] overlays sFeat+sW2

    const int tid  = threadIdx.x;
    const int lane = tid & 31;
    const int wid  = tid >> 5;            // 0..3
    const int ebase = blockIdx.x * 64;

    // stage W2 (rows 128..191 of g_We): 64*16 uint4
    {
        const uint4* gW2 = (const uint4*)g_We + 128 * 16;
        for (int i = tid; i < 64 * 16; i += 128) {
            int k = i >> 4, c = i & 15;
            *((uint4*)(sW2 + k * EG_LD) + c) = gW2[i];
        }
    }

    // front-batch indices
    int srcs[16], dsts[16];
    #pragma unroll
    for (int it = 0; it < 16; ++it) {
        int eidx = ebase + wid * 16 + it;
        srcs[it] = e[eidx];
        dsts[it] = e[N_EDGES + eidx];
    }

    // gather: sPre = y[dst]-y[src]; sXs = x[src]; sFeat = f16(e_feat)
    const uint2*  yh = (const uint2*)g_y;
    const uint2*  xh = (const uint2*)g_xh;
    const float4* f4 = (const float4*)efeat;
    #pragma unroll 4
    for (int it = 0; it < 16; ++it) {
        int r = wid * 16 + it;
        uint2 yd = yh[(size_t)dsts[it] * 32 + lane];
        uint2 ys = yh[(size_t)srcs[it] * 32 + lane];
        __half2 p0 = __hsub2(*(__half2*)&yd.x, *(__half2*)&ys.x);
        __half2 p1 = __hsub2(*(__half2*)&yd.y, *(__half2*)&ys.y);
        *(uint2*)(sPre + r * EG_LD + lane * 4) =
            make_uint2(*(unsigned*)&p0, *(unsigned*)&p1);
        *(uint2*)(sXs + r * EG_LD + lane * 4) = xh[(size_t)srcs[it] * 32 + lane];
        if (lane < 16) {
            float4 f = f4[(size_t)(ebase + r) * 16 + lane];
            __half2 f0 = __floats2half2_rn(f.x, f.y);
            __half2 f1 = __floats2half2_rn(f.z, f.w);
            *(uint2*)(sFeat + r * EF_LD2 + lane * 4) =
                make_uint2(*(unsigned*)&f0, *(unsigned*)&f1);
        }
        if (lane == 0) sDst[r] = dsts[it];
    }
    __syncthreads();

    // GEMM: C = efeat @ W2, K=64 (4 steps). warp (wm, wn): 32x64 patch
    const int wm = wid & 1, wn = wid >> 1;
    wmma::fragment<wmma::accumulator, 16, 16, 16, float> c[2][4];
    #pragma unroll
    for (int i = 0; i < 2; i++)
        #pragma unroll
        for (int j = 0; j < 4; j++) wmma::fill_fragment(c[i][j], 0.0f);

    #pragma unroll
    for (int k = 0; k < 4; ++k) {
        wmma::fragment<wmma::matrix_a, 16, 16, 16, __half, wmma::row_major> a[2];
        wmma::load_matrix_sync(a[0], sFeat + (wm * 32 +  0) * EF_LD2 + k * 16, EF_LD2);
        wmma::load_matrix_sync(a[1], sFeat + (wm * 32 + 16) * EF_LD2 + k * 16, EF_LD2);
        #pragma unroll
        for (int j = 0; j < 4; j++) {
            wmma::fragment<wmma::matrix_b, 16, 16, 16, __half, wmma::row_major> b;
            wmma::load_matrix_sync(b, sW2 + (k * 16) * EG_LD + wn * 64 + j * 16, EG_LD);
            wmma::mma_sync(c[0][j], a[0], b, c[0][j]);
            wmma::mma_sync(c[1][j], a[1], b, c[1][j]);
        }
    }
    __syncthreads();   // sFeat/sW2 reads done before sC overlays

    #pragma unroll
    for (int i = 0; i < 2; i++)
        #pragma unroll
        for (int j = 0; j < 4; j++)
            wmma::store_matrix_sync(sC + (wm * 32 + i * 16) * C_LD + wn * 64 + j * 16,
                                    c[i][j], C_LD, wmma::mem_row_major);
    __syncthreads();

    // epilogue: v = relu(C + pre + b) - x[src]; RED v (8B v4.f16, round-7 pattern)
    {
        float4 bv = ((const float4*)b_edge)[lane];
        #pragma unroll 4
        for (int it = 0; it < 16; ++it) {
            int m = wid * 16 + it;
            unsigned base = (unsigned)sDst[m] * 64u + lane * 2;
            const float* crow = sC + m * C_LD + lane * 4;
            uint2 pr = *(uint2*)(sPre + m * EG_LD + lane * 4);
            uint2 xs = *(uint2*)(sXs  + m * EG_LD + lane * 4);
            __half2 pr0 = *(__half2*)&pr.x, pr1 = *(__half2*)&pr.y;
            __half2 xs0 = *(__half2*)&xs.x, xs1 = *(__half2*)&xs.y;
            float v0 = fmaxf(crow[0] + __low2float(pr0)  + bv.x, 0.0f) - __low2float(xs0);
            float v1 = fmaxf(crow[1] + __high2float(pr0) + bv.y, 0.0f) - __high2float(xs0);
            float v2 = fmaxf(crow[2] + __low2float(pr1)  + bv.z, 0.0f) - __low2float(xs1);
            float v3 = fmaxf(crow[3] + __high2float(pr1) + bv.w, 0.0f) - __high2float(xs1);
            __half2 p0 = __floats2half2_rn(v0, v1);
            __half2 p1 = __floats2half2_rn(v2, v3);
            red_max_h4(&g_maxes[base], *(unsigned*)&p0, *(unsigned*)&p1);
        }
    }
}

// ---------- kernel 3: node MLP + residual (split-K, occ 2) ----------
__global__ __launch_bounds__(256, 2)
void node_kernel(const float* __restrict__ x, const float* __restrict__ b_mlp,
                 float* __restrict__ out) {
    extern __shared__ __align__(16) char smem[];
    __half* sA = (__half*)smem;                      // [128][A_LD_N]
    __half* sB = (__half*)(smem + SA_N_BYTES);       // [128][B_LD]
    float*  sC = (float*)smem;                       // overlays sA post-GEMM

    const int tid  = threadIdx.x;
    const int lane = tid & 31;
    const int wid  = tid >> 5;
    const int nbase = blockIdx.x * 128;
    const int wm = wid & 3, wn = wid >> 2;

    // stage B chunk 0
    {
        const uint4* gB = (const uint4*)g_Wm;
        for (int i = tid; i < 128 * 16; i += 256) {
            int k = i >> 4, c = i & 15;
            *((uint4*)(sB + k * B_LD) + c) = gB[i];
        }
    }

    // stage A: cols 0..127 = xh, 128..255 = x + max(relu - xs) (0 if empty)
    const uint2* xh = (const uint2*)g_xh;
    #pragma unroll 4
    for (int it = 0; it < 16; ++it) {
        int r = wid * 16 + it;
        int node = nbase + r;
        if (node < N_NODES) {
            uint2 a = xh[(size_t)node * 32 + lane];
            *(uint2*)(sA + r * A_LD_N + lane * 4) = a;
            uint2 mv = ((const uint2*)g_maxes)[(size_t)node * 32 + lane];
            *(uint2*)(sA + r * A_LD_N + 128 + lane * 4) =
                make_uint2(combine_max(mv.x, a.x), combine_max(mv.y, a.y));
        } else {
            *(uint2*)(sA + r * A_LD_N + lane * 4) = make_uint2(0u, 0u);
            *(uint2*)(sA + r * A_LD_N + 128 + lane * 4) = make_uint2(0u, 0u);
        }
    }
    __syncthreads();

    wmma::fragment<wmma::accumulator, 16, 16, 16, float> c[2][4];
    #pragma unroll
    for (int i = 0; i < 2; i++)
        #pragma unroll
        for (int j = 0; j < 4; j++) wmma::fill_fragment(c[i][j], 0.0f);

    // chunk 0: A cols 0..127, B rows 0..127
    #pragma unroll
    for (int k = 0; k < 8; ++k) {
        wmma::fragment<wmma::matrix_a, 16, 16, 16, __half, wmma::row_major> a[2];
        wmma::load_matrix_sync(a[0], sA + (wm * 32 +  0) * A_LD_N + k * 16, A_LD_N);
        wmma::load_matrix_sync(a[1], sA + (wm * 32 + 16) * A_LD_N + k * 16, A_LD_N);
        #pragma unroll
        for (int j = 0; j < 4; j++) {
            wmma::fragment<wmma::matrix_b, 16, 16, 16, __half, wmma::row_major> b;
            wmma::load_matrix_sync(b, sB + (k * 16) * B_LD + wn * 64 + j * 16, B_LD);
            wmma::mma_sync(c[0][j], a[0], b, c[0][j]);
            wmma::mma_sync(c[1][j], a[1], b, c[1][j]);
        }
    }
    __syncthreads();

    // stage B chunk 1
    {
        const uint4* gB = (const uint4*)g_Wm + 128 * 16;
        for (int i = tid; i < 128 * 16; i += 256) {
            int k = i >> 4, c = i & 15;
            *((uint4*)(sB + k * B_LD) + c) = gB[i];
        }
    }
    __syncthreads();

    // chunk 1: A cols 128..255, B rows 128..255
    #pragma unroll
    for (int k = 0; k < 8; ++k) {
        wmma::fragment<wmma::matrix_a, 16, 16, 16, __half, wmma::row_major> a[2];
        wmma::load_matrix_sync(a[0], sA + (wm * 32 +  0) * A_LD_N + 128 + k * 16, A_LD_N);
        wmma::load_matrix_sync(a[1], sA + (wm * 32 + 16) * A_LD_N + 128 + k * 16, A_LD_N);
        #pragma unroll
        for (int j = 0; j < 4; j++) {
            wmma::fragment<wmma::matrix_b, 16, 16, 16, __half, wmma::row_major> b;
            wmma::load_matrix_sync(b, sB + (k * 16) * B_LD + wn * 64 + j * 16, B_LD);
            wmma::mma_sync(c[0][j], a[0], b, c[0][j]);
            wmma::mma_sync(c[1][j], a[1], b, c[1][j]);
        }
    }
    __syncthreads();

    #pragma unroll
    for (int i = 0; i < 2; i++)
        #pragma unroll
        for (int j = 0; j < 4; j++)
            wmma::store_matrix_sync(sC + (wm * 32 + i * 16) * C_LD + wn * 64 + j * 16,
                                    c[i][j], C_LD, wmma::mem_row_major);
    __syncthreads();

    // epilogue: out = x + relu(C + b_mlp)
    {
        float4 bv = ((const float4*)b_mlp)[lane];
        #pragma unroll 4
        for (int it = 0; it < 16; ++it) {
            int m = wid * 16 + it;
            int node = nbase + m;
            if (node >= N_NODES) continue;
            const float* crow = sC + m * C_LD + lane * 4;
            float4 xv = ((const float4*)x)[(size_t)node * 32 + lane];
            float4 o;
            o.x = xv.x + fmaxf(crow[0] + bv.x, 0.0f);
            o.y = xv.y + fmaxf(crow[1] + bv.y, 0.0f);
            o.z = xv.z + fmaxf(crow[2] + bv.z, 0.0f);
            o.w = xv.w + fmaxf(crow[3] + bv.w, 0.0f);
            ((float4*)out)[(size_t)node * 32 + lane] = o;
        }
    }
}

extern "C" void kernel_launch(void* const* d_in, const int* in_sizes, int n_in,
                              void* d_out, int out_size) {
    const float* x     = (const float*)d_in[0];
    const int*   e     = (const int*)d_in[1];
    const float* efeat = (const float*)d_in[2];
    const float* We    = (const float*)d_in[3];
    const float* be    = (const float*)d_in[4];
    const float* Wm    = (const float*)d_in[5];
    const float* bm    = (const float*)d_in[6];
    float* out = (float*)d_out;

    cudaFuncSetAttribute(ygemm_kernel, cudaFuncAttributeMaxDynamicSharedMemorySize, SMEM_YG);
    cudaFuncSetAttribute(edge_kernel,  cudaFuncAttributeMaxDynamicSharedMemorySize, SMEM_EDGE);
    cudaFuncSetAttribute(node_kernel,  cudaFuncAttributeMaxDynamicSharedMemorySize, SMEM_NODE);

    prep_kernel<<<(N_NODES * WID / 4 + 255) / 256, 256>>>(x, We, Wm);
    ygemm_kernel<<<(N_NODES + 127) / 128, 256, SMEM_YG>>>();
    edge_kernel<<<N_EDGES / 64, 128, SMEM_EDGE>>>(e, efeat, be);
    node_kernel<<<(N_NODES + 127) / 128, 256, SMEM_NODE>>>(x, bm, out);
}

// round 11
// speedup vs baseline: 1.1023x; 1.1023x over previous
#include <cuda_runtime.h>
#include <cuda_fp16.h>
#include <mma.h>
#include <cstdint>

using namespace nvcuda;

#define N_NODES 100000
#define N_EDGES 640000
#define WID     128
#define NFEAT   64
#define KE      192      // WID + NFEAT
#define KM      256      // 2*WID
#define N_TILES (N_EDGES / 128)   // 5000
#define EDGE_GRID 296             // 2 blocks/SM

// ---- edge kernel smem (persistent) ----
#define A1_LD 136
#define A2_LD 72
#define B_LD  136
#define C_LD  132
#define EK_OFF_DST  0                         // int[128]
#define EK_OFF_BIAS 512                       // float[128]
#define EK_OFF_DIFF 1024                      // [128][136]h = 34816
#define EK_OFF_FEAT (1024 + 34816)            // [128][72]h = 18432 ; warp scratch overlays
#define EK_OFF_B    (EK_OFF_FEAT + 18432)     // [192][136]h = 52224
#define SMEM_EDGE   (EK_OFF_B + 52224)        // 106496 -> 2 blocks/SM
#define SCR_LD 20                              // per-warp scratch pitch (floats)

// ---- node kernel smem: sA [128][264]h (sC overlays) + sB chunk [128][136]h ----
#define A_LD_N  264
#define SA_N_BYTES (128*A_LD_N*2)             // 67584
#define SMEM_NODE (SA_N_BYTES + 128*B_LD*2)   // 102400 -> 2 blocks/SM

#define HNEG_INF2 0xFC00FC00u

// ---------- scratch (device globals) ----------
__device__ unsigned g_maxes[(size_t)N_NODES * (WID/2)];       // f16x2 words
__device__ __align__(16) __half g_xh[(size_t)N_NODES * WID];  // fp16 x image
__device__ __half   g_We[KE * WID];
__device__ __half   g_Wm[KM * WID];

__device__ __forceinline__ void red_max_h4(unsigned* addr, unsigned v01, unsigned v23) {
    unsigned short a = (unsigned short)(v01 & 0xFFFFu);
    unsigned short b = (unsigned short)(v01 >> 16);
    unsigned short c = (unsigned short)(v23 & 0xFFFFu);
    unsigned short d = (unsigned short)(v23 >> 16);
    asm volatile("red.global.v4.f16.max.noftz [%0], {%1, %2, %3, %4};"
                 :: "l"(addr), "h"(a), "h"(b), "h"(c), "h"(d) : "memory");
}
__device__ __forceinline__ unsigned fix_neginf(unsigned v) {
    if ((v & 0xFFFFu) == 0xFC00u) v &= 0xFFFF0000u;
    if ((v >> 16)     == 0xFC00u) v &= 0x0000FFFFu;
    return v;
}

// ---------- kernel 0: weights+x -> fp16, reset segment-max buffer ----------
__global__ void prep_kernel(const float* __restrict__ x,
                            const float* __restrict__ We, const float* __restrict__ Wm) {
    int i = blockIdx.x * blockDim.x + threadIdx.x;
    if (i < N_NODES * WID / 4) {
        float4 v = ((const float4*)x)[i];
        __half2 h0 = __floats2half2_rn(v.x, v.y);
        __half2 h1 = __floats2half2_rn(v.z, v.w);
        ((uint2*)g_xh)[i] = make_uint2(*(unsigned*)&h0, *(unsigned*)&h1);
    }
    if (i < N_NODES * (WID/2) / 4)
        ((uint4*)g_maxes)[i] = make_uint4(HNEG_INF2, HNEG_INF2, HNEG_INF2, HNEG_INF2);
    if (i < KE * WID) g_We[i] = __float2half_rn(We[i]);
    if (i < KM * WID) g_Wm[i] = __float2half_rn(Wm[i]);
}

// ---------- kernel 1: persistent fused edge MLP + segment-max ----------
// grid = 296 persistent blocks, 256 threads; each block loops over 128-edge tiles
__global__ __launch_bounds__(256, 2)
void edge_kernel(const int* __restrict__ e, const float* __restrict__ efeat,
                 const float* __restrict__ b_edge) {
    extern __shared__ __align__(16) char smem[];
    int*    sDst  = (int*)(smem + EK_OFF_DST);
    float*  sBias = (float*)(smem + EK_OFF_BIAS);
    __half* sDiff = (__half*)(smem + EK_OFF_DIFF);   // [128][A1_LD]
    __half* sFeat = (__half*)(smem + EK_OFF_FEAT);   // [128][A2_LD]; scratch overlays post-GEMM
    __half* sB    = (__half*)(smem + EK_OFF_B);      // [KE][B_LD], persistent

    const int tid  = threadIdx.x;
    const int lane = tid & 31;
    const int wid  = tid >> 5;           // 0..7
    const int wm   = wid & 3, wn = wid >> 2;
    float* myScr = (float*)(smem + EK_OFF_FEAT) + wid * (16 * SCR_LD);  // 1280 B/warp

    // ---- one-time staging: W_edge + bias ----
    {
        const uint4* gB = (const uint4*)g_We;
        for (int i = tid; i < KE * 16; i += 256) {
            int k = i >> 4, c = i & 15;
            *((uint4*)(sB + k * B_LD) + c) = gB[i];
        }
        if (tid < 128) sBias[tid] = b_edge[tid];
    }

    const uint2*  xh = (const uint2*)g_xh;
    const float4* f4 = (const float4*)efeat;

    for (int tile = blockIdx.x; tile < N_TILES; tile += EDGE_GRID) {
        const int ebase = tile * 128;
        __syncthreads();   // prior epilogue done (sDiff/sDst/scratch) before overwrite

        // front-batch edge indices
        int srcs[16], dsts[16];
        #pragma unroll
        for (int it = 0; it < 16; ++it) {
            int eidx = ebase + wid * 16 + it;
            srcs[it] = e[eidx];
            dsts[it] = e[N_EDGES + eidx];
        }

        // gather: sDiff = xh[dst]-xh[src]; sFeat = fp16(e_feat)
        #pragma unroll 4
        for (int it = 0; it < 16; ++it) {
            int r = wid * 16 + it;
            uint2 a = xh[(size_t)dsts[it] * 32 + lane];
            uint2 b = xh[(size_t)srcs[it] * 32 + lane];
            __half2 d0 = __hsub2(*(__half2*)&a.x, *(__half2*)&b.x);
            __half2 d1 = __hsub2(*(__half2*)&a.y, *(__half2*)&b.y);
            *(uint2*)(sDiff + r * A1_LD + lane * 4) =
                make_uint2(*(unsigned*)&d0, *(unsigned*)&d1);
            if (lane < 16) {
                float4 f = f4[(size_t)(ebase + r) * 16 + lane];
                __half2 f0 = __floats2half2_rn(f.x, f.y);
                __half2 f1 = __floats2half2_rn(f.z, f.w);
                *(uint2*)(sFeat + r * A2_LD + lane * 4) =
                    make_uint2(*(unsigned*)&f0, *(unsigned*)&f1);
            }
            if (lane == 0) sDst[r] = dsts[it];
        }
        __syncthreads();

        // GEMM: warp (wm, wn) -> rows wm*32..+32, cols wn*64..+64; K=192
        wmma::fragment<wmma::accumulator, 16, 16, 16, float> c[2][4];
        #pragma unroll
        for (int i = 0; i < 2; i++)
            #pragma unroll
            for (int j = 0; j < 4; j++) wmma::fill_fragment(c[i][j], 0.0f);

        #pragma unroll
        for (int k = 0; k < 12; ++k) {
            wmma::fragment<wmma::matrix_a, 16, 16, 16, __half, wmma::row_major> a[2];
            if (k < 8) {
                wmma::load_matrix_sync(a[0], sDiff + (wm * 32 +  0) * A1_LD + k * 16, A1_LD);
                wmma::load_matrix_sync(a[1], sDiff + (wm * 32 + 16) * A1_LD + k * 16, A1_LD);
            } else {
                wmma::load_matrix_sync(a[0], sFeat + (wm * 32 +  0) * A2_LD + (k - 8) * 16, A2_LD);
                wmma::load_matrix_sync(a[1], sFeat + (wm * 32 + 16) * A2_LD + (k - 8) * 16, A2_LD);
            }
            #pragma unroll
            for (int j = 0; j < 4; j++) {
                wmma::fragment<wmma::matrix_b, 16, 16, 16, __half, wmma::row_major> b;
                wmma::load_matrix_sync(b, sB + (k * 16) * B_LD + wn * 64 + j * 16, B_LD);
                wmma::mma_sync(c[0][j], a[0], b, c[0][j]);
                wmma::mma_sync(c[1][j], a[1], b, c[1][j]);
            }
        }
        __syncthreads();   // all sFeat reads done before warp scratch overlays it

        // per-warp fragment epilogue: one 16x16 frag at a time through 1.25KB scratch
        const int rl = lane & 15;          // row within fragment
        const int ch = lane >> 4;          // col-half (8 cols each)
        #pragma unroll
        for (int i = 0; i < 2; i++) {
            #pragma unroll
            for (int j = 0; j < 4; j++) {
                wmma::store_matrix_sync(myScr, c[i][j], SCR_LD, wmma::mem_row_major);
                __syncwarp();
                int grow = wm * 32 + i * 16 + rl;
                int gcol = wn * 64 + j * 16 + ch * 8;
                float4 c0 = *(float4*)(myScr + rl * SCR_LD + ch * 8);
                float4 c1 = *(float4*)(myScr + rl * SCR_LD + ch * 8 + 4);
                __syncwarp();   // scratch reads done before next store
                float4 b0 = *(float4*)(sBias + gcol);
                float4 b1 = *(float4*)(sBias + gcol + 4);
                uint4 dv = *(uint4*)(sDiff + grow * A1_LD + gcol);
                __half2 d0 = *(__half2*)&dv.x, d1 = *(__half2*)&dv.y;
                __half2 d2 = *(__half2*)&dv.z, d3 = *(__half2*)&dv.w;
                int dstn = sDst[grow];
                float v0 = fmaxf(c0.x + b0.x, 0.0f) + __low2float(d0);
                float v1 = fmaxf(c0.y + b0.y, 0.0f) + __high2float(d0);
                float v2 = fmaxf(c0.z + b0.z, 0.0f) + __low2float(d1);
                float v3 = fmaxf(c0.w + b0.w, 0.0f) + __high2float(d1);
                float v4 = fmaxf(c1.x + b1.x, 0.0f) + __low2float(d2);
                float v5 = fmaxf(c1.y + b1.y, 0.0f) + __high2float(d2);
                float v6 = fmaxf(c1.z + b1.z, 0.0f) + __low2float(d3);
                float v7 = fmaxf(c1.w + b1.w, 0.0f) + __high2float(d3);
                __half2 p0 = __floats2half2_rn(v0, v1);
                __half2 p1 = __floats2half2_rn(v2, v3);
                __half2 p2 = __floats2half2_rn(v4, v5);
                __half2 p3 = __floats2half2_rn(v6, v7);
                unsigned* base = g_maxes + (unsigned)dstn * 64u + (gcol >> 1);
                red_max_h4(base,     *(unsigned*)&p0, *(unsigned*)&p1);
                red_max_h4(base + 2, *(unsigned*)&p2, *(unsigned*)&p3);
            }
        }
    }
}

// ---------- kernel 2: node MLP + residual (split-K, occ 2; r7 proven) ----------
__global__ __launch_bounds__(256, 2)
void node_kernel(const float* __restrict__ x, const float* __restrict__ b_mlp,
                 float* __restrict__ out) {
    extern __shared__ __align__(16) char smem[];
    __half* sA = (__half*)smem;                      // [128][A_LD_N]
    __half* sB = (__half*)(smem + SA_N_BYTES);       // [128][B_LD]
    float*  sC = (float*)smem;                       // overlays sA post-GEMM

    const int tid  = threadIdx.x;
    const int lane = tid & 31;
    const int wid  = tid >> 5;
    const int nbase = blockIdx.x * 128;
    const int wm = wid & 3, wn = wid >> 2;

    // stage B chunk 0
    {
        const uint4* gB = (const uint4*)g_Wm;
        for (int i = tid; i < 128 * 16; i += 256) {
            int k = i >> 4, c = i & 15;
            *((uint4*)(sB + k * B_LD) + c) = gB[i];
        }
    }

    // stage A: cols 0..127 = xh, 128..255 = maxes (fp16, -inf -> 0)
    const uint2* xh = (const uint2*)g_xh;
    #pragma unroll 4
    for (int it = 0; it < 16; ++it) {
        int r = wid * 16 + it;
        int node = nbase + r;
        if (node < N_NODES) {
            *(uint2*)(sA + r * A_LD_N + lane * 4) = xh[(size_t)node * 32 + lane];
            uint2 mv = ((const uint2*)g_maxes)[(size_t)node * 32 + lane];
            *(uint2*)(sA + r * A_LD_N + 128 + lane * 4) =
                make_uint2(fix_neginf(mv.x), fix_neginf(mv.y));
        } else {
            *(uint2*)(sA + r * A_LD_N + lane * 4) = make_uint2(0u, 0u);
            *(uint2*)(sA + r * A_LD_N + 128 + lane * 4) = make_uint2(0u, 0u);
        }
    }
    __syncthreads();

    wmma::fragment<wmma::accumulator, 16, 16, 16, float> c[2][4];
    #pragma unroll
    for (int i = 0; i < 2; i++)
        #pragma unroll
        for (int j = 0; j < 4; j++) wmma::fill_fragment(c[i][j], 0.0f);

    // chunk 0
    #pragma unroll
    for (int k = 0; k < 8; ++k) {
        wmma::fragment<wmma::matrix_a, 16, 16, 16, __half, wmma::row_major> a[2];
        wmma::load_matrix_sync(a[0], sA + (wm * 32 +  0) * A_LD_N + k * 16, A_LD_N);
        wmma::load_matrix_sync(a[1], sA + (wm * 32 + 16) * A_LD_N + k * 16, A_LD_N);
        #pragma unroll
        for (int j = 0; j < 4; j++) {
            wmma::fragment<wmma::matrix_b, 16, 16, 16, __half, wmma::row_major> b;
            wmma::load_matrix_sync(b, sB + (k * 16) * B_LD + wn * 64 + j * 16, B_LD);
            wmma::mma_sync(c[0][j], a[0], b, c[0][j]);
            wmma::mma_sync(c[1][j], a[1], b, c[1][j]);
        }
    }
    __syncthreads();

    // stage B chunk 1
    {
        const uint4* gB = (const uint4*)g_Wm + 128 * 16;
        for (int i = tid; i < 128 * 16; i += 256) {
            int k = i >> 4, c = i & 15;
            *((uint4*)(sB + k * B_LD) + c) = gB[i];
        }
    }
    __syncthreads();

    // chunk 1
    #pragma unroll
    for (int k = 0; k < 8; ++k) {
        wmma::fragment<wmma::matrix_a, 16, 16, 16, __half, wmma::row_major> a[2];
        wmma::load_matrix_sync(a[0], sA + (wm * 32 +  0) * A_LD_N + 128 + k * 16, A_LD_N);
        wmma::load_matrix_sync(a[1], sA + (wm * 32 + 16) * A_LD_N + 128 + k * 16, A_LD_N);
        #pragma unroll
        for (int j = 0; j < 4; j++) {
            wmma::fragment<wmma::matrix_b, 16, 16, 16, __half, wmma::row_major> b;
            wmma::load_matrix_sync(b, sB + (k * 16) * B_LD + wn * 64 + j * 16, B_LD);
            wmma::mma_sync(c[0][j], a[0], b, c[0][j]);
            wmma::mma_sync(c[1][j], a[1], b, c[1][j]);
        }
    }
    __syncthreads();

    #pragma unroll
    for (int i = 0; i < 2; i++)
        #pragma unroll
        for (int j = 0; j < 4; j++)
            wmma::store_matrix_sync(sC + (wm * 32 + i * 16) * C_LD + wn * 64 + j * 16,
                                    c[i][j], C_LD, wmma::mem_row_major);
    __syncthreads();

    {
        float4 bv = ((const float4*)b_mlp)[lane];
        #pragma unroll 4
        for (int it = 0; it < 16; ++it) {
            int m = wid * 16 + it;
            int node = nbase + m;
            if (node >= N_NODES) continue;
            const float* crow = sC + m * C_LD + lane * 4;
            float4 xv = ((const float4*)x)[(size_t)node * 32 + lane];
            float4 o;
            o.x = xv.x + fmaxf(crow[0] + bv.x, 0.0f);
            o.y = xv.y + fmaxf(crow[1] + bv.y, 0.0f);
            o.z = xv.z + fmaxf(crow[2] + bv.z, 0.0f);
            o.w = xv.w + fmaxf(crow[3] + bv.w, 0.0f);
            ((float4*)out)[(size_t)node * 32 + lane] = o;
        }
    }
}

extern "C" void kernel_launch(void* const* d_in, const int* in_sizes, int n_in,
                              void* d_out, int out_size) {
    const float* x     = (const float*)d_in[0];
    const int*   e     = (const int*)d_in[1];
    const float* efeat = (const float*)d_in[2];
    const float* We    = (const float*)d_in[3];
    const float* be    = (const float*)d_in[4];
    const float* Wm    = (const float*)d_in[5];
    const float* bm    = (const float*)d_in[6];
    float* out = (float*)d_out;

    cudaFuncSetAttribute(edge_kernel, cudaFuncAttributeMaxDynamicSharedMemorySize, SMEM_EDGE);
    cudaFuncSetAttribute(node_kernel, cudaFuncAttributeMaxDynamicSharedMemorySize, SMEM_NODE);

    prep_kernel<<<(N_NODES * WID / 4 + 255) / 256, 256>>>(x, We, Wm);
    edge_kernel<<<EDGE_GRID, 256, SMEM_EDGE>>>(e, efeat, be);
    node_kernel<<<(N_NODES + 127) / 128, 256, SMEM_NODE>>>(x, bm, out);
}

// round 12
// speedup vs baseline: 1.1320x; 1.0269x over previous
#include <cuda_runtime.h>
#include <cuda_fp16.h>
#include <mma.h>
#include <cstdint>

using namespace nvcuda;

#define N_NODES 100000
#define N_EDGES 640000
#define WID     128
#define NFEAT   64
#define KE      192      // WID + NFEAT
#define KM      256      // 2*WID
#define N_TILES (N_EDGES / 128)   // 5000
#define EDGE_GRID 296             // 2 blocks/SM

// ---- edge kernel smem (persistent, r11 proven) ----
#define A1_LD 136
#define A2_LD 72
#define B_LD  136
#define C_LD  132
#define EK_OFF_DST  0                         // int[128]
#define EK_OFF_BIAS 512                       // float[128]
#define EK_OFF_DIFF 1024                      // [128][136]h = 34816
#define EK_OFF_FEAT (1024 + 34816)            // [128][72]h = 18432 ; warp scratch overlays
#define EK_OFF_B    (EK_OFF_FEAT + 18432)     // [192][136]h = 52224
#define SMEM_EDGE   (EK_OFF_B + 52224)        // 106496 -> 2 blocks/SM
#define SCR_LD 20                              // per-warp scratch pitch (floats)

// ---- node kernel smem (64-row tiles, occ 3) ----
#define A_LD_N  264
#define NT_ROWS 64
#define SA_N_BYTES (NT_ROWS*A_LD_N*2)         // 33792 (== 64*C_LD*4, exact C overlay)
#define SMEM_NODE (SA_N_BYTES + 128*B_LD*2)   // 68608 -> 3 blocks/SM

#define HNEG_INF2 0xFC00FC00u

// ---------- scratch (device globals) ----------
__device__ unsigned g_maxes[(size_t)N_NODES * (WID/2)];       // f16x2 words
__device__ __align__(16) __half g_xh[(size_t)N_NODES * WID];  // fp16 x image
__device__ __half   g_We[KE * WID];
__device__ __half   g_Wm[KM * WID];

__device__ __forceinline__ void red_max_h4(unsigned* addr, unsigned v01, unsigned v23) {
    unsigned short a = (unsigned short)(v01 & 0xFFFFu);
    unsigned short b = (unsigned short)(v01 >> 16);
    unsigned short c = (unsigned short)(v23 & 0xFFFFu);
    unsigned short d = (unsigned short)(v23 >> 16);
    asm volatile("red.global.v4.f16.max.noftz [%0], {%1, %2, %3, %4};"
                 :: "l"(addr), "h"(a), "h"(b), "h"(c), "h"(d) : "memory");
}
__device__ __forceinline__ unsigned fix_neginf(unsigned v) {
    if ((v & 0xFFFFu) == 0xFC00u) v &= 0xFFFF0000u;
    if ((v >> 16)     == 0xFC00u) v &= 0x0000FFFFu;
    return v;
}

// ---------- kernel 0: weights+x -> fp16, reset segment-max buffer ----------
__global__ void prep_kernel(const float* __restrict__ x,
                            const float* __restrict__ We, const float* __restrict__ Wm) {
    int i = blockIdx.x * blockDim.x + threadIdx.x;
    if (i < N_NODES * WID / 4) {
        float4 v = ((const float4*)x)[i];
        __half2 h0 = __floats2half2_rn(v.x, v.y);
        __half2 h1 = __floats2half2_rn(v.z, v.w);
        ((uint2*)g_xh)[i] = make_uint2(*(unsigned*)&h0, *(unsigned*)&h1);
    }
    if (i < N_NODES * (WID/2) / 4)
        ((uint4*)g_maxes)[i] = make_uint4(HNEG_INF2, HNEG_INF2, HNEG_INF2, HNEG_INF2);
    if (i < KE * WID) g_We[i] = __float2half_rn(We[i]);
    if (i < KM * WID) g_Wm[i] = __float2half_rn(Wm[i]);
}

// ---------- kernel 1: persistent fused edge MLP + segment-max (r11 proven) ----------
__global__ __launch_bounds__(256, 2)
void edge_kernel(const int* __restrict__ e, const float* __restrict__ efeat,
                 const float* __restrict__ b_edge) {
    extern __shared__ __align__(16) char smem[];
    int*    sDst  = (int*)(smem + EK_OFF_DST);
    float*  sBias = (float*)(smem + EK_OFF_BIAS);
    __half* sDiff = (__half*)(smem + EK_OFF_DIFF);   // [128][A1_LD]
    __half* sFeat = (__half*)(smem + EK_OFF_FEAT);   // [128][A2_LD]; scratch overlays post-GEMM
    __half* sB    = (__half*)(smem + EK_OFF_B);      // [KE][B_LD], persistent

    const int tid  = threadIdx.x;
    const int lane = tid & 31;
    const int wid  = tid >> 5;           // 0..7
    const int wm   = wid & 3, wn = wid >> 2;
    float* myScr = (float*)(smem + EK_OFF_FEAT) + wid * (16 * SCR_LD);  // 1280 B/warp

    // one-time staging: W_edge + bias
    {
        const uint4* gB = (const uint4*)g_We;
        for (int i = tid; i < KE * 16; i += 256) {
            int k = i >> 4, c = i & 15;
            *((uint4*)(sB + k * B_LD) + c) = gB[i];
        }
        if (tid < 128) sBias[tid] = b_edge[tid];
    }

    const uint2*  xh = (const uint2*)g_xh;
    const float4* f4 = (const float4*)efeat;

    for (int tile = blockIdx.x; tile < N_TILES; tile += EDGE_GRID) {
        const int ebase = tile * 128;
        __syncthreads();   // prior epilogue done before overwrite

        int srcs[16], dsts[16];
        #pragma unroll
        for (int it = 0; it < 16; ++it) {
            int eidx = ebase + wid * 16 + it;
            srcs[it] = e[eidx];
            dsts[it] = e[N_EDGES + eidx];
        }

        #pragma unroll 4
        for (int it = 0; it < 16; ++it) {
            int r = wid * 16 + it;
            uint2 a = xh[(size_t)dsts[it] * 32 + lane];
            uint2 b = xh[(size_t)srcs[it] * 32 + lane];
            __half2 d0 = __hsub2(*(__half2*)&a.x, *(__half2*)&b.x);
            __half2 d1 = __hsub2(*(__half2*)&a.y, *(__half2*)&b.y);
            *(uint2*)(sDiff + r * A1_LD + lane * 4) =
                make_uint2(*(unsigned*)&d0, *(unsigned*)&d1);
            if (lane < 16) {
                float4 f = f4[(size_t)(ebase + r) * 16 + lane];
                __half2 f0 = __floats2half2_rn(f.x, f.y);
                __half2 f1 = __floats2half2_rn(f.z, f.w);
                *(uint2*)(sFeat + r * A2_LD + lane * 4) =
                    make_uint2(*(unsigned*)&f0, *(unsigned*)&f1);
            }
            if (lane == 0) sDst[r] = dsts[it];
        }
        __syncthreads();

        wmma::fragment<wmma::accumulator, 16, 16, 16, float> c[2][4];
        #pragma unroll
        for (int i = 0; i < 2; i++)
            #pragma unroll
            for (int j = 0; j < 4; j++) wmma::fill_fragment(c[i][j], 0.0f);

        #pragma unroll
        for (int k = 0; k < 12; ++k) {
            wmma::fragment<wmma::matrix_a, 16, 16, 16, __half, wmma::row_major> a[2];
            if (k < 8) {
                wmma::load_matrix_sync(a[0], sDiff + (wm * 32 +  0) * A1_LD + k * 16, A1_LD);
                wmma::load_matrix_sync(a[1], sDiff + (wm * 32 + 16) * A1_LD + k * 16, A1_LD);
            } else {
                wmma::load_matrix_sync(a[0], sFeat + (wm * 32 +  0) * A2_LD + (k - 8) * 16, A2_LD);
                wmma::load_matrix_sync(a[1], sFeat + (wm * 32 + 16) * A2_LD + (k - 8) * 16, A2_LD);
            }
            #pragma unroll
            for (int j = 0; j < 4; j++) {
                wmma::fragment<wmma::matrix_b, 16, 16, 16, __half, wmma::row_major> b;
                wmma::load_matrix_sync(b, sB + (k * 16) * B_LD + wn * 64 + j * 16, B_LD);
                wmma::mma_sync(c[0][j], a[0], b, c[0][j]);
                wmma::mma_sync(c[1][j], a[1], b, c[1][j]);
            }
        }
        __syncthreads();   // sFeat reads done before warp scratch overlays it

        const int rl = lane & 15;
        const int ch = lane >> 4;
        #pragma unroll
        for (int i = 0; i < 2; i++) {
            #pragma unroll
            for (int j = 0; j < 4; j++) {
                wmma::store_matrix_sync(myScr, c[i][j], SCR_LD, wmma::mem_row_major);
                __syncwarp();
                int grow = wm * 32 + i * 16 + rl;
                int gcol = wn * 64 + j * 16 + ch * 8;
                float4 c0 = *(float4*)(myScr + rl * SCR_LD + ch * 8);
                float4 c1 = *(float4*)(myScr + rl * SCR_LD + ch * 8 + 4);
                __syncwarp();
                float4 b0 = *(float4*)(sBias + gcol);
                float4 b1 = *(float4*)(sBias + gcol + 4);
                uint4 dv = *(uint4*)(sDiff + grow * A1_LD + gcol);
                __half2 d0 = *(__half2*)&dv.x, d1 = *(__half2*)&dv.y;
                __half2 d2 = *(__half2*)&dv.z, d3 = *(__half2*)&dv.w;
                int dstn = sDst[grow];
                float v0 = fmaxf(c0.x + b0.x, 0.0f) + __low2float(d0);
                float v1 = fmaxf(c0.y + b0.y, 0.0f) + __high2float(d0);
                float v2 = fmaxf(c0.z + b0.z, 0.0f) + __low2float(d1);
                float v3 = fmaxf(c0.w + b0.w, 0.0f) + __high2float(d1);
                float v4 = fmaxf(c1.x + b1.x, 0.0f) + __low2float(d2);
                float v5 = fmaxf(c1.y + b1.y, 0.0f) + __high2float(d2);
                float v6 = fmaxf(c1.z + b1.z, 0.0f) + __low2float(d3);
                float v7 = fmaxf(c1.w + b1.w, 0.0f) + __high2float(d3);
                __half2 p0 = __floats2half2_rn(v0, v1);
                __half2 p1 = __floats2half2_rn(v2, v3);
                __half2 p2 = __floats2half2_rn(v4, v5);
                __half2 p3 = __floats2half2_rn(v6, v7);
                unsigned* base = g_maxes + (unsigned)dstn * 64u + (gcol >> 1);
                red_max_h4(base,     *(unsigned*)&p0, *(unsigned*)&p1);
                red_max_h4(base + 2, *(unsigned*)&p2, *(unsigned*)&p3);
            }
        }
    }
}

// ---------- kernel 2: node MLP + residual (64-row tiles, occ 3) ----------
__global__ __launch_bounds__(256, 3)
void node_kernel(const float* __restrict__ x, const float* __restrict__ b_mlp,
                 float* __restrict__ out) {
    extern __shared__ __align__(16) char smem[];
    __half* sA = (__half*)smem;                      // [64][A_LD_N]
    __half* sB = (__half*)(smem + SA_N_BYTES);       // [128][B_LD] (one K-chunk)
    float*  sC = (float*)smem;                       // [64][C_LD] overlays sA post-GEMM

    const int tid  = threadIdx.x;
    const int lane = tid & 31;
    const int wid  = tid >> 5;
    const int nbase = blockIdx.x * NT_ROWS;
    const int wm = wid & 1, wn = wid >> 1;   // 2 x 4 warp grid, 32x32 patch each

    // stage B chunk 0 (W_mlp rows 0..127)
    {
        const uint4* gB = (const uint4*)g_Wm;
        for (int i = tid; i < 128 * 16; i += 256) {
            int k = i >> 4, c = i & 15;
            *((uint4*)(sB + k * B_LD) + c) = gB[i];
        }
    }

    // stage A: 8 rows per warp; cols 0..127 = xh, 128..255 = maxes (-inf -> 0)
    const uint2* xh = (const uint2*)g_xh;
    #pragma unroll
    for (int it = 0; it < 8; ++it) {
        int r = wid * 8 + it;
        int node = nbase + r;
        if (node < N_NODES) {
            *(uint2*)(sA + r * A_LD_N + lane * 4) = xh[(size_t)node * 32 + lane];
            uint2 mv = ((const uint2*)g_maxes)[(size_t)node * 32 + lane];
            *(uint2*)(sA + r * A_LD_N + 128 + lane * 4) =
                make_uint2(fix_neginf(mv.x), fix_neginf(mv.y));
        } else {
            *(uint2*)(sA + r * A_LD_N + lane * 4) = make_uint2(0u, 0u);
            *(uint2*)(sA + r * A_LD_N + 128 + lane * 4) = make_uint2(0u, 0u);
        }
    }
    __syncthreads();

    wmma::fragment<wmma::accumulator, 16, 16, 16, float> c[2][2];
    #pragma unroll
    for (int i = 0; i < 2; i++)
        #pragma unroll
        for (int j = 0; j < 2; j++) wmma::fill_fragment(c[i][j], 0.0f);

    // chunk 0: A cols 0..127 (x part), B rows 0..127
    #pragma unroll
    for (int k = 0; k < 8; ++k) {
        wmma::fragment<wmma::matrix_a, 16, 16, 16, __half, wmma::row_major> a[2];
        wmma::load_matrix_sync(a[0], sA + (wm * 32 +  0) * A_LD_N + k * 16, A_LD_N);
        wmma::load_matrix_sync(a[1], sA + (wm * 32 + 16) * A_LD_N + k * 16, A_LD_N);
        #pragma unroll
        for (int j = 0; j < 2; j++) {
            wmma::fragment<wmma::matrix_b, 16, 16, 16, __half, wmma::row_major> b;
            wmma::load_matrix_sync(b, sB + (k * 16) * B_LD + wn * 32 + j * 16, B_LD);
            wmma::mma_sync(c[0][j], a[0], b, c[0][j]);
            wmma::mma_sync(c[1][j], a[1], b, c[1][j]);
        }
    }
    __syncthreads();

    // stage B chunk 1 (W_mlp rows 128..255)
    {
        const uint4* gB = (const uint4*)g_Wm + 128 * 16;
        for (int i = tid; i < 128 * 16; i += 256) {
            int k = i >> 4, c = i & 15;
            *((uint4*)(sB + k * B_LD) + c) = gB[i];
        }
    }
    __syncthreads();

    // chunk 1: A cols 128..255 (maxes part), B rows 128..255
    #pragma unroll
    for (int k = 0; k < 8; ++k) {
        wmma::fragment<wmma::matrix_a, 16, 16, 16, __half, wmma::row_major> a[2];
        wmma::load_matrix_sync(a[0], sA + (wm * 32 +  0) * A_LD_N + 128 + k * 16, A_LD_N);
        wmma::load_matrix_sync(a[1], sA + (wm * 32 + 16) * A_LD_N + 128 + k * 16, A_LD_N);
        #pragma unroll
        for (int j = 0; j < 2; j++) {
            wmma::fragment<wmma::matrix_b, 16, 16, 16, __half, wmma::row_major> b;
            wmma::load_matrix_sync(b, sB + (k * 16) * B_LD + wn * 32 + j * 16, B_LD);
            wmma::mma_sync(c[0][j], a[0], b, c[0][j]);
            wmma::mma_sync(c[1][j], a[1], b, c[1][j]);
        }
    }
    __syncthreads();   // sA reads done before C overlays it

    #pragma unroll
    for (int i = 0; i < 2; i++)
        #pragma unroll
        for (int j = 0; j < 2; j++)
            wmma::store_matrix_sync(sC + (wm * 32 + i * 16) * C_LD + wn * 32 + j * 16,
                                    c[i][j], C_LD, wmma::mem_row_major);
    __syncthreads();

    // epilogue: out = x + relu(C + b_mlp); 8 rows per warp
    {
        float4 bv = ((const float4*)b_mlp)[lane];
        #pragma unroll
        for (int it = 0; it < 8; ++it) {
            int m = wid * 8 + it;
            int node = nbase + m;
            if (node >= N_NODES) continue;
            const float* crow = sC + m * C_LD + lane * 4;
            float4 xv = ((const float4*)x)[(size_t)node * 32 + lane];
            float4 o;
            o.x = xv.x + fmaxf(crow[0] + bv.x, 0.0f);
            o.y = xv.y + fmaxf(crow[1] + bv.y, 0.0f);
            o.z = xv.z + fmaxf(crow[2] + bv.z, 0.0f);
            o.w = xv.w + fmaxf(crow[3] + bv.w, 0.0f);
            ((float4*)out)[(size_t)node * 32 + lane] = o;
        }
    }
}

extern "C" void kernel_launch(void* const* d_in, const int* in_sizes, int n_in,
                              void* d_out, int out_size) {
    const float* x     = (const float*)d_in[0];
    const int*   e     = (const int*)d_in[1];
    const float* efeat = (const float*)d_in[2];
    const float* We    = (const float*)d_in[3];
    const float* be    = (const float*)d_in[4];
    const float* Wm    = (const float*)d_in[5];
    const float* bm    = (const float*)d_in[6];
    float* out = (float*)d_out;

    cudaFuncSetAttribute(edge_kernel, cudaFuncAttributeMaxDynamicSharedMemorySize, SMEM_EDGE);
    cudaFuncSetAttribute(node_kernel, cudaFuncAttributeMaxDynamicSharedMemorySize, SMEM_NODE);

    prep_kernel<<<(N_NODES * WID / 4 + 255) / 256, 256>>>(x, We, Wm);
    edge_kernel<<<EDGE_GRID, 256, SMEM_EDGE>>>(e, efeat, be);
    node_kernel<<<(N_NODES + NT_ROWS - 1) / NT_ROWS, 256, SMEM_NODE>>>(x, bm, out);
}